// round 3
// baseline (speedup 1.0000x reference)
#include <cuda_runtime.h>

#define TPB    128
#define BAND   16          // output rows per block
#define HH     384
#define ROWF   1536        // W*C floats per row
#define ROW4   384         // float4 blocks per row
#define CB     3           // column-blocks per row (3*128 = 384)
#define NBANDS (HH / BAND)

static __device__ __forceinline__ int hrefl(int h) {
    // reflect-101 along height; used only for h in [-2, HH+1]
    h = (h < 0) ? -h : h;
    return (h >= HH) ? (2 * HH - 2 - h) : h;
}

// Gaussian taps for ksize=5, sigma=1.1 (OpenCV default), normalized.
__device__ __constant__ const float C0 = 0.07076630f;  // w[0] = w[4]
__device__ __constant__ const float C1 = 0.24446028f;  // w[1] = w[3]
__device__ __constant__ const float C2 = 0.36954642f;  // w[2]

// Load row hh (pre-reflect), horizontally blur this thread's float4 column c.
// Halo comes from the neighbors' float4 blocks (clamped); width reflect-101
// is a pure permutation of the loaded values for c in {0,1,382,383}.
static __device__ __forceinline__ float4 hb_row(
    const float4* __restrict__ bin, int hh, int c,
    int cm2, int cm1, int cp1, int cp2)
{
    const float4* __restrict__ rp = bin + (long)hrefl(hh) * ROW4;
    float4 Lm2 = __ldg(rp + cm2);
    float4 Lm1 = __ldg(rp + cm1);
    float4 O   = __ldg(rp + c);
    float4 Rp1 = __ldg(rp + cp1);
    float4 Rp2 = __ldg(rp + cp2);

    // Extended window e[j] = flat(4c-6+j); e[6..9] = O.
    float e0  = Lm2.z, e1  = Lm2.w, e2  = Lm1.x, e3  = Lm1.y, e4  = Lm1.z, e5  = Lm1.w;
    float e10 = Rp1.x, e11 = Rp1.y, e12 = Rp1.z, e13 = Rp1.w, e14 = Rp2.x, e15 = Rp2.y;

    if (c == 0) {            // flats -6..-1 -> reflected flats {6,7,8,3,4,5}
        e0 = Rp1.z; e1 = Rp1.w; e2 = Rp2.x; e3 = O.w; e4 = Rp1.x; e5 = Rp1.y;
    } else if (c == 1) {     // flats -2,-1 -> {4,5} = own .x,.y
        e0 = O.x; e1 = O.y;
    }
    if (c == ROW4 - 1) {     // flats 1536..1541 -> {1530,1531,1532,1527,1528,1529}
        e10 = Lm1.z; e11 = Lm1.w; e12 = O.x; e13 = Lm2.w; e14 = Lm1.x; e15 = Lm1.y;
    } else if (c == ROW4 - 2) { // flats 1536,1537 -> {1530,1531} = own .z,.w
        e14 = O.z; e15 = O.w;
    }

    // Horizontal taps at flat offsets {-6,-3,0,+3,+6}.
    float4 hb;
    hb.x = C0 * (e0 + e12) + C1 * (e3  + O.w) + C2 * O.x;
    hb.y = C0 * (e1 + e13) + C1 * (e4  + e10) + C2 * O.y;
    hb.z = C0 * (e2 + e14) + C1 * (e5  + e11) + C2 * O.z;
    hb.w = C0 * (e3 + e15) + C1 * (O.x + e12) + C2 * O.w;
    return hb;
}

__global__ void __launch_bounds__(TPB, 8)
gauss5_kernel(const float* __restrict__ x, float* __restrict__ y)
{
    const int c  = blockIdx.x * TPB + threadIdx.x;  // float4 column, 0..383
    const int h0 = blockIdx.y * BAND;
    const long img = blockIdx.z;

    const float4* __restrict__ bin  = (const float4*)(x + img * (long)(HH * ROWF));
    float4*       __restrict__ bout = (float4*)      (y + img * (long)(HH * ROWF)) + c;

    const int cm2 = max(c - 2, 0),        cm1 = max(c - 1, 0);
    const int cp1 = min(c + 1, ROW4 - 1), cp2 = min(c + 2, ROW4 - 1);

    // 5-row sliding window of horizontally-blurred float4s (registers only).
    float4 w0 = hb_row(bin, h0 - 2, c, cm2, cm1, cp1, cp2);
    float4 w1 = hb_row(bin, h0 - 1, c, cm2, cm1, cp1, cp2);
    float4 w2 = hb_row(bin, h0,     c, cm2, cm1, cp1, cp2);
    float4 w3 = hb_row(bin, h0 + 1, c, cm2, cm1, cp1, cp2);

    #pragma unroll
    for (int r = 0; r < BAND; r++) {
        float4 w4 = hb_row(bin, h0 + r + 2, c, cm2, cm1, cp1, cp2);

        // Vertical pass (symmetric taps), thread-private.
        float4 o;
        o.x = C0 * (w0.x + w4.x) + C1 * (w1.x + w3.x) + C2 * w2.x;
        o.y = C0 * (w0.y + w4.y) + C1 * (w1.y + w3.y) + C2 * w2.y;
        o.z = C0 * (w0.z + w4.z) + C1 * (w1.z + w3.z) + C2 * w2.z;
        o.w = C0 * (w0.w + w4.w) + C1 * (w1.w + w3.w) + C2 * w2.w;

        bout[(long)(h0 + r) * ROW4] = o;

        w0 = w1; w1 = w2; w2 = w3; w3 = w4;
    }
}

extern "C" void kernel_launch(void* const* d_in, const int* in_sizes, int n_in,
                              void* d_out, int out_size)
{
    const float* x = (const float*)d_in[0];
    float* y = (float*)d_out;
    const int batch = in_sizes[0] / (HH * ROWF);   // 64
    dim3 grid(CB, NBANDS, batch);
    gauss5_kernel<<<grid, TPB>>>(x, y);
}

// round 4
// speedup vs baseline: 1.1027x; 1.1027x over previous
#include <cuda_runtime.h>

#define TPB    192        // one thread per 8 floats of a 1536-float row
#define BAND   16         // output rows per block
#define HH     384
#define ROWF   1536       // W*C floats per row
#define NBANDS (HH / BAND)

static __device__ __forceinline__ int hrefl(int h) {
    // reflect-101 along height; used only for h in [-2, HH+1]
    h = (h < 0) ? -h : h;
    return (h >= HH) ? (2 * HH - 2 - h) : h;
}

// Gaussian taps for ksize=5, sigma=1.1 (OpenCV default), normalized.
#define C0 0.07076630f    /* w[0] = w[4] */
#define C1 0.24446028f    /* w[1] = w[3] */
#define C2 0.36954642f    /* w[2]        */

struct F8 { float v[8]; };

// Load row h (pre-reflect) and horizontally blur this thread's 8 floats
// (flats 8t..8t+7). Halo comes from neighbor lanes' registers via SHFL;
// warp-edge lanes (0,31) use predicated global loads; image width edges
// (t==0, t==TPB-1) fold reflect-101 into a register permutation.
static __device__ __forceinline__ F8 hb_row(
    const float* __restrict__ ib, int h, int t, int lane)
{
    const float* __restrict__ rp = ib + (long)hrefl(h) * ROWF + 8 * t;
    float4 Cb = *(const float4*)(rp);       // flats 8t   .. 8t+3
    float4 Db = *(const float4*)(rp + 4);   // flats 8t+4 .. 8t+7

    // e[k] = flat(8t - 6 + k), k = 0..19
    float e0  = __shfl_up_sync(0xffffffffu, Cb.z, 1);   // 8t-6
    float e1  = __shfl_up_sync(0xffffffffu, Cb.w, 1);   // 8t-5
    float e2  = __shfl_up_sync(0xffffffffu, Db.x, 1);   // 8t-4
    float e3  = __shfl_up_sync(0xffffffffu, Db.y, 1);   // 8t-3
    float e4  = __shfl_up_sync(0xffffffffu, Db.z, 1);   // 8t-2
    float e5  = __shfl_up_sync(0xffffffffu, Db.w, 1);   // 8t-1
    float e14 = __shfl_down_sync(0xffffffffu, Cb.x, 1); // 8t+8
    float e15 = __shfl_down_sync(0xffffffffu, Cb.y, 1); // 8t+9
    float e16 = __shfl_down_sync(0xffffffffu, Cb.z, 1); // 8t+10
    float e17 = __shfl_down_sync(0xffffffffu, Cb.w, 1); // 8t+11
    float e18 = __shfl_down_sync(0xffffffffu, Db.x, 1); // 8t+12
    float e19 = __shfl_down_sync(0xffffffffu, Db.y, 1); // 8t+13

    // Warp-edge fallback: lanes 0 / 31 fetch the cross-warp halo directly.
    if (lane == 0 && t > 0) {
        float2 a = *(const float2*)(rp - 6);
        float4 b = *(const float4*)(rp - 4);
        e0 = a.x; e1 = a.y; e2 = b.x; e3 = b.y; e4 = b.z; e5 = b.w;
    }
    if (lane == 31 && t < TPB - 1) {
        float4 b = *(const float4*)(rp + 8);
        float2 a = *(const float2*)(rp + 12);
        e14 = b.x; e15 = b.y; e16 = b.z; e17 = b.w; e18 = a.x; e19 = a.y;
    }
    // Image width edges: reflect-101 permutation of already-held values.
    if (t == 0) {            // flats -6..-1 -> {6,7,8,3,4,5}
        e0 = Db.z; e1 = Db.w; e2 = e14; e3 = Cb.w; e4 = Db.x; e5 = Db.y;
    }
    if (t == TPB - 1) {      // flats 1536..1541 -> {1530,1531,1532,1527,1528,1529}
        e14 = Cb.z; e15 = Cb.w; e16 = Db.x; e17 = e5; e18 = Cb.x; e19 = Cb.y;
    }

    const float e6 = Cb.x, e7 = Cb.y, e8 = Cb.z, e9 = Cb.w;
    const float e10 = Db.x, e11 = Db.y, e12 = Db.z, e13 = Db.w;

    // Horizontal taps at flat offsets {-6,-3,0,+3,+6}: o[j] uses e[j..j+12].
    F8 o;
    o.v[0] = C0 * (e0 + e12) + C1 * (e3  + e9)  + C2 * e6;
    o.v[1] = C0 * (e1 + e13) + C1 * (e4  + e10) + C2 * e7;
    o.v[2] = C0 * (e2 + e14) + C1 * (e5  + e11) + C2 * e8;
    o.v[3] = C0 * (e3 + e15) + C1 * (e6  + e12) + C2 * e9;
    o.v[4] = C0 * (e4 + e16) + C1 * (e7  + e13) + C2 * e10;
    o.v[5] = C0 * (e5 + e17) + C1 * (e8  + e14) + C2 * e11;
    o.v[6] = C0 * (e6 + e18) + C1 * (e9  + e15) + C2 * e12;
    o.v[7] = C0 * (e7 + e19) + C1 * (e10 + e16) + C2 * e13;
    return o;
}

__global__ void __launch_bounds__(TPB, 4)
gauss5_kernel(const float* __restrict__ x, float* __restrict__ y)
{
    const int t    = threadIdx.x;
    const int lane = t & 31;
    const int h0   = blockIdx.x * BAND;
    const long img = blockIdx.y;

    const float* __restrict__ ib = x + img * (long)(HH * ROWF);
    float*       __restrict__ ob = y + img * (long)(HH * ROWF) + 8 * t;

    // 5-row sliding window of horizontally-blurred values (registers only).
    F8 w0 = hb_row(ib, h0 - 2, t, lane);
    F8 w1 = hb_row(ib, h0 - 1, t, lane);
    F8 w2 = hb_row(ib, h0,     t, lane);
    F8 w3 = hb_row(ib, h0 + 1, t, lane);

    #pragma unroll 4
    for (int r = 0; r < BAND; r++) {
        F8 w4 = hb_row(ib, h0 + r + 2, t, lane);

        // Vertical pass (symmetric taps), thread-private.
        float4 oa, obv;
        oa.x  = C0 * (w0.v[0] + w4.v[0]) + C1 * (w1.v[0] + w3.v[0]) + C2 * w2.v[0];
        oa.y  = C0 * (w0.v[1] + w4.v[1]) + C1 * (w1.v[1] + w3.v[1]) + C2 * w2.v[1];
        oa.z  = C0 * (w0.v[2] + w4.v[2]) + C1 * (w1.v[2] + w3.v[2]) + C2 * w2.v[2];
        oa.w  = C0 * (w0.v[3] + w4.v[3]) + C1 * (w1.v[3] + w3.v[3]) + C2 * w2.v[3];
        obv.x = C0 * (w0.v[4] + w4.v[4]) + C1 * (w1.v[4] + w3.v[4]) + C2 * w2.v[4];
        obv.y = C0 * (w0.v[5] + w4.v[5]) + C1 * (w1.v[5] + w3.v[5]) + C2 * w2.v[5];
        obv.z = C0 * (w0.v[6] + w4.v[6]) + C1 * (w1.v[6] + w3.v[6]) + C2 * w2.v[6];
        obv.w = C0 * (w0.v[7] + w4.v[7]) + C1 * (w1.v[7] + w3.v[7]) + C2 * w2.v[7];

        float4* op = (float4*)(ob + (long)(h0 + r) * ROWF);
        op[0] = oa;
        op[1] = obv;

        w0 = w1; w1 = w2; w2 = w3; w3 = w4;
    }
}

extern "C" void kernel_launch(void* const* d_in, const int* in_sizes, int n_in,
                              void* d_out, int out_size)
{
    const float* x = (const float*)d_in[0];
    float* y = (float*)d_out;
    const int batch = in_sizes[0] / (HH * ROWF);   // 64
    dim3 grid(NBANDS, batch);
    gauss5_kernel<<<grid, TPB>>>(x, y);
}